// round 17
// baseline (speedup 1.0000x reference)
#include <cuda_runtime.h>
#include <cuda_fp16.h>
#include <math.h>
#include <stdint.h>

// ---------------- problem constants ----------------
#define Bv     64
#define Lv     256
#define Ev     1600
#define Pv     100
#define Nv     400          // P*4 (no padding anywhere)
#define NTILE  80           // per-CTA n tile (5 * 80 = 400 exact)
#define Mv     16384        // B*L
#define Kv     1600
#define NCH    50           // Kv/32

// output layout (floats)
#define OFF_D0   6400
#define OFF_D1   556928
#define OFF_D2   1084928
#define OFF_FC   1606592

// ---------------- device scratch ----------------
static __device__ __half g_Yt[(size_t)Nv * Mv]; // Y^T [n][m], fp16 (13.1 MB)
static __device__ float g_S[Mv];                 // row sum of squares
static __device__ float g_P2[Pv];                // proto sum of squares
// fp16 chunked operands: row = 32 k values = 64 B
static __device__ __align__(16) unsigned char g_Xc[(size_t)NCH * Mv * 64];   // [kc][m][64]
static __device__ __align__(16) unsigned char g_Bc[(size_t)NCH * Nv * 64];   // [kc][n][64]

// ---------------- smem layout (per CTA, dynamic) ----------------
#define ROWB      80                     // padded smem row stride (64B data + 16 pad)
#define ASZ       (128 * ROWB)           // 10240
#define BOFF      ASZ
#define BUFSTRIDE (ASZ + 80 * ROWB)      // 16640
#define SMEM_DYN  (2 * BUFSTRIDE)        // 33280

__device__ __forceinline__ uint32_t s2u(const void* p) {
    uint32_t a;
    asm("{ .reg .u64 t; cvta.to.shared.u64 t, %1; cvt.u32.u64 %0, t; }" : "=r"(a) : "l"(p));
    return a;
}

#define CP_ASYNC16(dst, src) \
    asm volatile("cp.async.cg.shared.global [%0], [%1], 16;" :: "r"(dst), "l"(src) : "memory")
#define CP_COMMIT() asm volatile("cp.async.commit_group;" ::: "memory")
#define CP_WAIT(n)  asm volatile("cp.async.wait_group %0;" :: "n"(n) : "memory")

#define LDM_X4(r0, r1, r2, r3, a) \
    asm volatile("ldmatrix.sync.aligned.m8n8.x4.shared.b16 {%0,%1,%2,%3}, [%4];" \
                 : "=r"(r0), "=r"(r1), "=r"(r2), "=r"(r3) : "r"(a))
#define LDM_X2(r0, r1, a) \
    asm volatile("ldmatrix.sync.aligned.m8n8.x2.shared.b16 {%0,%1}, [%2];" \
                 : "=r"(r0), "=r"(r1) : "r"(a))

// fp16 accumulate, fp16 inputs
#define MMAF16(d, a, b) \
    asm volatile("mma.sync.aligned.m16n8k16.row.col.f16.f16.f16.f16 " \
                 "{%0,%1}, {%2,%3,%4,%5}, {%6,%7}, {%0,%1};" \
                 : "+r"((d)[0]), "+r"((d)[1]) \
                 : "r"((a)[0]), "r"((a)[1]), "r"((a)[2]), "r"((a)[3]), \
                   "r"((b)[0]), "r"((b)[1]))

// ---------------- fused prep: X->fp16 chunked + sumsq, proto->fp16 chunked + P2 -----
__global__ void __launch_bounds__(256)
prep_kernel(const float* __restrict__ X, const float* __restrict__ proto,
            float* __restrict__ out) {
    if (blockIdx.x < 2048) {
        // ---- X path: warp per row ----
        int m    = blockIdx.x * 8 + (threadIdx.x >> 5);
        int lane = threadIdx.x & 31;
        const float4* src = reinterpret_cast<const float4*>(X + (size_t)m * Ev);
        float ssq = 0.0f;
        #pragma unroll
        for (int it = 0; it < 7; ++it) {
            int j = lane + it * 32;
            if (j < 200) {
                float4 a = src[2 * j], b = src[2 * j + 1];
                ssq += a.x * a.x + a.y * a.y + a.z * a.z + a.w * a.w
                     + b.x * b.x + b.y * b.y + b.z * b.z + b.w * b.w;
                __half2 p0 = __floats2half2_rn(a.x, a.y);
                __half2 p1 = __floats2half2_rn(a.z, a.w);
                __half2 p2 = __floats2half2_rn(b.x, b.y);
                __half2 p3 = __floats2half2_rn(b.z, b.w);
                uint4 w;
                w.x = *reinterpret_cast<uint32_t*>(&p0);
                w.y = *reinterpret_cast<uint32_t*>(&p1);
                w.z = *reinterpret_cast<uint32_t*>(&p2);
                w.w = *reinterpret_cast<uint32_t*>(&p3);
                int kc = j >> 2, dk = j & 3;           // 32 k per chunk = 4 groups of 8
                *reinterpret_cast<uint4*>(g_Xc + ((size_t)kc * Mv + m) * 64 + dk * 16) = w;
            }
        }
        #pragma unroll
        for (int o = 16; o > 0; o >>= 1) ssq += __shfl_xor_sync(0xffffffffu, ssq, o);
        if (lane == 0) g_S[m] = ssq;
    } else {
        // ---- B path: block per proto ----
        int p = blockIdx.x - 2048;                          // 0..99
        if (p == 0 && threadIdx.x < 2 * Bv) out[OFF_FC + threadIdx.x] = 0.0f;
        __shared__ float red[256];
        float s = 0.0f;
        for (int i = threadIdx.x; i < Ev * 4; i += 256) {
            int e = i >> 2, t = i & 3;
            float v = proto[(size_t)p * (Ev * 4) + i];
            s += v * v;
            int n = 4 * p + t;
            int kc = e >> 5, dk = e & 31;
            *reinterpret_cast<__half*>(
                g_Bc + ((size_t)kc * Nv + n) * 64 + dk * 2) = __float2half_rn(v);
        }
        red[threadIdx.x] = s;
        __syncthreads();
        for (int st = 128; st > 0; st >>= 1) {
            if (threadIdx.x < st) red[threadIdx.x] += red[threadIdx.x + st];
            __syncthreads();
        }
        if (threadIdx.x == 0) g_P2[p] = red[0];
    }
}

// ---------------- HMMA GEMM: Yt[n][m] = sum_k X[m][k]*W[k][n] ----------------
// grid (5, 128): 128x80 per CTA; 8 warps (4M x 2N), warp tile 32x40; chunk K=32.
// Pure fp16 accumulation; 4 CTAs/SM.
__device__ __forceinline__ void issue_chunk(uint32_t sbuf, int kc, int m0, int n0, int tid) {
    const char* asrc = (const char*)(g_Xc + ((size_t)kc * Mv + m0) * 64);
    #pragma unroll
    for (int u = 0; u < 2; ++u) {
        int i = tid + u * 256;                        // 512 = 128 rows * 4 quads
        CP_ASYNC16(sbuf + (i >> 2) * ROWB + (i & 3) * 16, asrc + i * 16);
    }
    const char* bsrc = (const char*)(g_Bc + ((size_t)kc * Nv + n0) * 64);
    {
        int i = tid;                                  // 320 = 80 rows * 4 quads
        CP_ASYNC16(sbuf + BOFF + (i >> 2) * ROWB + (i & 3) * 16, bsrc + i * 16);
    }
    if (tid < 64) {
        int i = tid + 256;
        CP_ASYNC16(sbuf + BOFF + (i >> 2) * ROWB + (i & 3) * 16, bsrc + i * 16);
    }
    CP_COMMIT();
}

__global__ void __launch_bounds__(256, 4)
gemm_mma_kernel() {
    extern __shared__ __align__(128) char smem[];
    const uint32_t sb = s2u(smem);
    const int tid  = threadIdx.x;
    const int wid  = tid >> 5;
    const int lane = tid & 31;
    const int nb = blockIdx.x;              // 0..4
    const int m0 = blockIdx.y * 128;
    const int n0 = nb * NTILE;

    const int m_warp = (wid >> 1) * 32;     // 0,32,64,96
    const int n_warp = (wid & 1) * 40;      // 0,40

    const uint32_t aA = sb + (uint32_t)(m_warp + (lane & 15)) * ROWB + (lane >> 4) * 16;
    const uint32_t aB4 = sb + BOFF +
        (uint32_t)(n_warp + ((lane >> 4) << 3) + (lane & 7)) * ROWB + ((lane >> 3) & 1) * 16;
    const int l15 = lane & 15;
    const uint32_t aB2 = sb + BOFF +
        (uint32_t)(n_warp + 32 + (l15 & 7)) * ROWB + ((l15 >> 3) & 1) * 16;

    uint32_t acc16[2][5][2];
    #pragma unroll
    for (int i = 0; i < 2; ++i)
        #pragma unroll
        for (int j = 0; j < 5; ++j) {
            acc16[i][j][0] = 0u; acc16[i][j][1] = 0u;
        }

    // prologue: chunks 0,1 in flight
    issue_chunk(sb, 0, m0, n0, tid);
    issue_chunk(sb + BUFSTRIDE, 1, m0, n0, tid);
    CP_WAIT(1);
    __syncthreads();

    for (int kc = 0; kc < NCH; ++kc) {
        const uint32_t bo = (kc & 1) ? BUFSTRIDE : 0;
        // ---- compute chunk kc: 2 k16 steps ----
        #pragma unroll
        for (int ks = 0; ks < 2; ++ks) {
            uint32_t afr[2][4];
            #pragma unroll
            for (int mf = 0; mf < 2; ++mf)
                LDM_X4(afr[mf][0], afr[mf][1], afr[mf][2], afr[mf][3],
                       aA + bo + mf * (16 * ROWB) + ks * 32);
            uint32_t bfr[5][2];
            #pragma unroll
            for (int p = 0; p < 2; ++p)
                LDM_X4(bfr[2 * p][0], bfr[2 * p][1], bfr[2 * p + 1][0], bfr[2 * p + 1][1],
                       aB4 + bo + p * (16 * ROWB) + ks * 32);
            LDM_X2(bfr[4][0], bfr[4][1], aB2 + bo + ks * 32);
            #pragma unroll
            for (int mf = 0; mf < 2; ++mf)
                #pragma unroll
                for (int nf = 0; nf < 5; ++nf)
                    MMAF16(acc16[mf][nf], afr[mf], bfr[nf]);
        }
        // ---- refill freed buffer with chunk kc+2 ----
        if (kc < NCH - 1) {
            __syncthreads();
            if (kc < NCH - 2) {
                issue_chunk(sb + bo, kc + 2, m0, n0, tid);
                CP_WAIT(1);
            } else {
                CP_WAIT(0);
            }
            __syncthreads();
        }
    }

    // ---- epilogue: fp16 acc -> g_Yt[n][m] fp16 (N exact: no guards) ----
    #pragma unroll
    for (int mf = 0; mf < 2; ++mf) {
        const int mbase = m0 + m_warp + mf * 16 + (lane >> 2);
        #pragma unroll
        for (int nf = 0; nf < 5; ++nf) {
            const int nbase = n0 + n_warp + nf * 8 + 2 * (lane & 3);
            __half2 h0 = *reinterpret_cast<__half2*>(&acc16[mf][nf][0]);
            __half2 h1 = *reinterpret_cast<__half2*>(&acc16[mf][nf][1]);
            g_Yt[(size_t)nbase * Mv + mbase]           = __low2half(h0);
            g_Yt[(size_t)(nbase + 1) * Mv + mbase]     = __high2half(h0);
            g_Yt[(size_t)nbase * Mv + mbase + 8]       = __low2half(h1);
            g_Yt[(size_t)(nbase + 1) * Mv + mbase + 8] = __high2half(h1);
        }
    }
}

// ---------------- distances + per-(b,p) min + fused fc ----------------
__global__ void __launch_bounds__(256)
dist_kernel(float* __restrict__ out, const float* __restrict__ fcw) {
    int idx  = blockIdx.x * 8 + (threadIdx.x >> 5);   // (b,p), grid 800 -> 6400
    int lane = threadIdx.x & 31;
    int p = idx % Pv;
    int b = idx / Pv;
    int g = (p < 34) ? 0 : (p < 67) ? 1 : 2;
    int d = g + 1;
    int Lout = Lv - 3 * d;                             // 253/250/247
    int pbase = (g == 0) ? 0 : (g == 1) ? 34 : 67;
    int nf = (g == 0) ? 34 : 33;
    size_t dbase = (g == 0) ? OFF_D0 : (g == 1) ? OFF_D1 : OFF_D2;
    float* orow = out + dbase + ((size_t)b * nf + (p - pbase)) * Lout;

    const __half* y0 = g_Yt + (size_t)(p * 4) * Mv + b * Lv;
    const float* s0 = g_S + b * Lv;
    const float p2 = g_P2[p];

    float mn = 3.402823466e38f;
    #pragma unroll
    for (int it = 0; it < 7; ++it) {                   // l <= 223 always in-bounds
        int l = lane + it * 32;
        float xp = 0.0f, x2 = 0.0f;
        #pragma unroll
        for (int k = 0; k < 4; ++k) {
            xp += __half2float(y0[(size_t)k * Mv + l + k * d]);
            x2 += s0[l + k * d];
        }
        float val = sqrtf(fabsf(x2 - 2.0f * xp + p2));
        orow[l] = val;
        mn = fminf(mn, val);
    }
    {   // tail: l = lane + 224, guard against Lout
        int l = lane + 224;
        if (l < Lout) {
            float xp = 0.0f, x2 = 0.0f;
            #pragma unroll
            for (int k = 0; k < 4; ++k) {
                xp += __half2float(y0[(size_t)k * Mv + l + k * d]);
                x2 += s0[l + k * d];
            }
            float val = sqrtf(fabsf(x2 - 2.0f * xp + p2));
            orow[l] = val;
            mn = fminf(mn, val);
        }
    }
    #pragma unroll
    for (int o = 16; o > 0; o >>= 1) mn = fminf(mn, __shfl_xor_sync(0xffffffffu, mn, o));
    if (lane == 0) {
        out[b * Pv + p] = mn;
        atomicAdd(out + OFF_FC + b * 2 + 0, mn * fcw[p]);
        atomicAdd(out + OFF_FC + b * 2 + 1, mn * fcw[Pv + p]);
    }
}

// ---------------- launch ----------------
extern "C" void kernel_launch(void* const* d_in, const int* in_sizes, int n_in,
                              void* d_out, int out_size) {
    const float* emb   = (const float*)d_in[0];   // [64,256,1600]
    const float* proto = (const float*)d_in[1];   // [100,1600,4]
    const float* fcw   = (const float*)d_in[2];   // [2,100]
    float* out = (float*)d_out;

    static int smem_set = 0;
    if (!smem_set) {
        cudaFuncSetAttribute(gemm_mma_kernel,
                             cudaFuncAttributeMaxDynamicSharedMemorySize, SMEM_DYN);
        smem_set = 1;
    }

    prep_kernel<<<2148, 256>>>(emb, proto, out);
    gemm_mma_kernel<<<dim3(5, 128), 256, SMEM_DYN>>>();
    dist_kernel<<<800, 256>>>(out, fcw);
}